// round 11
// baseline (speedup 1.0000x reference)
#include <cuda_runtime.h>
#include <math.h>
#include <stdint.h>

#define HIST     50
#define NUMD     32
#define NCAT     8
#define CATD     16
#define REGD     32
#define INDIM    242
#define HID      64
#define KEXP     64
#define TOPK     8
#define HASHB    32768
#define GEOB     4096
#define B_ROWS   524288

#define THREADS  512
#define TILE_M   128
#define NTILES   (B_ROWS / TILE_M)   // 4096
#define XS       132                  // floats per k-row (16B-aligned stride)
#define LGS      68                   // logit scratch row stride (floats)
#define CSTR     34                   // cand row stride (float2 units)

// ---- SMEM layout (byte offsets). H/H2/logits/cand alias the X region. ----
#define OFF_X      0                 // 242*132*4 = 127776
#define OFF_H      0                 //  64*132*4 = 33792 (X dead after L1)
#define OFF_CAND   0                 // 128*34*8 = 34816 (H dead after L2)
#define OFF_H2     34816             //  33792 (ends 68608)
#define OFF_LG     69632             // 128*68*4 = 34816 (ends 104448 < 127776)
#define OFF_W1     127872            // 242*64*4 = 61952
#define OFF_W2     189824            // 16384
#define OFF_W3     206208            // 16384
#define OFF_B1     222592
#define OFF_B2     222848
#define OFF_B3     223104
#define SMEM_TOTAL 223360

typedef unsigned long long u64;

// ---- packed f32x2 helpers (FFMA2: bit-identical fp32 math, 2 FMA/instr) ----
__device__ __forceinline__ u64 pk2(float lo, float hi) {
    u64 r;
    asm("mov.b64 %0, {%1, %2};" : "=l"(r) : "f"(lo), "f"(hi));
    return r;
}
__device__ __forceinline__ void upk2(u64 p, float& lo, float& hi) {
    asm("mov.b64 {%0, %1}, %2;" : "=f"(lo), "=f"(hi) : "l"(p));
}
__device__ __forceinline__ void fma2(u64& d, u64 a, u64 b) {
    asm("fma.rn.f32x2 %0, %1, %2, %0;" : "+l"(d) : "l"(a), "l"(b));
}

__device__ __forceinline__ float gelu_exact(float x) {
    return 0.5f * x * (1.0f + erff(x * 0.70710678118654752440f));
}

// ---- register-tiled GEMM: thread = 2 rows x 8 cols, k ascending (bitwise fp32) ----
// A: k-major [K][XS]; W: k-major [K][64].
// acc[r][cp] = packed f32x2 over col pair (c0+2cp, c0+2cp+1) for row r0+r.
// x loaded as float2 (row pair), duplicated (2 pk2); W pairs native u64 (no movs).
template<int K>
__device__ __forceinline__ void gemm_rt(const float* __restrict__ A,
                                        const float* __restrict__ W,
                                        int r0, int c0,
                                        u64 acc[2][4]) {
    #pragma unroll
    for (int r = 0; r < 2; ++r)
        #pragma unroll
        for (int cp = 0; cp < 4; ++cp) acc[r][cp] = 0ull;

    const float* a = A + r0;
    const float* w = W + c0;
    #pragma unroll 4
    for (int k = 0; k < K; ++k) {
        const float2 xv = *reinterpret_cast<const float2*>(a);
        const ulonglong2 wq0 = *reinterpret_cast<const ulonglong2*>(w);
        const ulonglong2 wq1 = *reinterpret_cast<const ulonglong2*>(w + 4);
        const u64 x0 = pk2(xv.x, xv.x);
        const u64 x1 = pk2(xv.y, xv.y);
        fma2(acc[0][0], x0, wq0.x);
        fma2(acc[0][1], x0, wq0.y);
        fma2(acc[0][2], x0, wq1.x);
        fma2(acc[0][3], x0, wq1.y);
        fma2(acc[1][0], x1, wq0.x);
        fma2(acc[1][1], x1, wq0.y);
        fma2(acc[1][2], x1, wq1.x);
        fma2(acc[1][3], x1, wq1.y);
        a += XS; w += 64;
    }
}

// gelu(acc + bias) -> k-major DST[c][r] for the next layer (float2 per col)
__device__ __forceinline__ void act_store(const u64 acc[2][4],
                                          const float* __restrict__ bb8,
                                          float* __restrict__ DST,
                                          int r0, int c0) {
    float gv[2][8];
    #pragma unroll
    for (int r = 0; r < 2; ++r)
        #pragma unroll
        for (int cp = 0; cp < 4; ++cp)
            upk2(acc[r][cp], gv[r][2 * cp], gv[r][2 * cp + 1]);
    #pragma unroll
    for (int r = 0; r < 2; ++r)
        #pragma unroll
        for (int c = 0; c < 8; ++c)
            gv[r][c] = gelu_exact(gv[r][c] + bb8[c]);
    #pragma unroll
    for (int c = 0; c < 8; ++c)
        *reinterpret_cast<float2*>(DST + (c0 + c) * XS + r0) =
            make_float2(gv[0][c], gv[1][c]);
}

__global__ __launch_bounds__(THREADS, 1)
void gating_kernel(const float* __restrict__ hist,
                   const float* __restrict__ num,
                   const int*   __restrict__ cat,
                   const int*   __restrict__ region,
                   const float* __restrict__ catT,
                   const float* __restrict__ regT,
                   const float* __restrict__ W1, const float* __restrict__ b1,
                   const float* __restrict__ W2, const float* __restrict__ b2,
                   const float* __restrict__ W3, const float* __restrict__ b3,
                   float* __restrict__ out)
{
    extern __shared__ __align__(16) char sm[];
    const int tid  = threadIdx.x;
    const int wid  = tid >> 5;
    const int lane = tid & 31;

    float*  sx   = (float*)(sm + OFF_X);
    float*  sh   = (float*)(sm + OFF_H);
    float*  sh2  = (float*)(sm + OFF_H2);
    float*  slg  = (float*)(sm + OFF_LG);
    float2* cand = (float2*)(sm + OFF_CAND);
    float*  sw1  = (float*)(sm + OFF_W1);
    float*  sw2  = (float*)(sm + OFF_W2);
    float*  sw3  = (float*)(sm + OFF_W3);

    // ---- stage weights (k-major, direct copy) + biases ----
    for (int i = tid; i < INDIM * 64 / 4; i += THREADS)
        ((float4*)sw1)[i] = ((const float4*)W1)[i];
    for (int i = tid; i < 64 * 64 / 4; i += THREADS) {
        ((float4*)sw2)[i] = ((const float4*)W2)[i];
        ((float4*)sw3)[i] = ((const float4*)W3)[i];
    }
    if (tid < 64) {
        ((float*)(sm + OFF_B1))[tid] = b1[tid];
        ((float*)(sm + OFF_B2))[tid] = b2[tid];
        ((float*)(sm + OFF_B3))[tid] = b3[tid];
    }
    __syncthreads();

    // GEMM mapping: warp = 8 rows x 64 cols; thread = 2 rows x 8 cols
    const int warpRow = wid * 8;
    const int r0 = warpRow + (lane >> 3) * 2;   // rowsub 0..3
    const int c0 = (lane & 7) * 8;              // colsub 0..7

    float bb1[8], bb2[8], bb3[8];
    #pragma unroll
    for (int c = 0; c < 8; ++c) {
        bb1[c] = ((const float*)(sm + OFF_B1))[c0 + c];
        bb2[c] = ((const float*)(sm + OFF_B2))[c0 + c];
        bb3[c] = ((const float*)(sm + OFF_B3))[c0 + c];
    }

    // gather lane roles for cat: j = embedding slot, e = float4 quarter
    const int cj = lane >> 2;          // 0..7
    const int ce = lane & 3;           // 0..3

    for (int tile = blockIdx.x; tile < NTILES; tile += gridDim.x) {
        const int rbase = tile * TILE_M;

        // ---- hoisted zeroing of this tile's output (drains under gather/GEMM) ----
        {
            float4* obase = reinterpret_cast<float4*>(out + (size_t)rbase * KEXP);
            const float4 z = make_float4(0.f, 0.f, 0.f, 0.f);
            #pragma unroll
            for (int j = 0; j < 4; ++j) obase[tid + j * THREADS] = z;
        }

        // ---- gather -> X[k][r] (k-major); warp = 8 rows, lanes spread k ----
        {
            const int wrow = wid * 8;
            #pragma unroll 2
            for (int rr = 0; rr < 8; ++rr) {
                const int lr = wrow + rr;
                const size_t row = (size_t)(rbase + lr);
                sx[lane * XS + lr] = hist[row * HIST + lane];
                if (lane < HIST - 32)
                    sx[(32 + lane) * XS + lr] = hist[row * HIST + 32 + lane];
                sx[(HIST + lane) * XS + lr] = num[row * NUMD + lane];
                // cat: one idx LDG + one float4 LDG per lane
                {
                    int idx = cat[row * NCAT + cj];
                    idx = min(max(idx, 0), HASHB - 1);
                    const float4 cv = *reinterpret_cast<const float4*>(
                        catT + ((size_t)(cj * HASHB + idx)) * CATD + 4 * ce);
                    const int kb = HIST + NUMD + cj * CATD + 4 * ce;
                    sx[(kb + 0) * XS + lr] = cv.x;
                    sx[(kb + 1) * XS + lr] = cv.y;
                    sx[(kb + 2) * XS + lr] = cv.z;
                    sx[(kb + 3) * XS + lr] = cv.w;
                }
                int rid = region[row];
                rid = min(max(rid, 0), GEOB - 1);
                sx[(HIST + NUMD + NCAT * CATD + lane) * XS + lr] = regT[(size_t)rid * REGD + lane];
            }
        }
        __syncthreads();

        u64 acc[2][4];

        // ---- layer 1 (K=242) ----
        gemm_rt<INDIM>(sx, sw1, r0, c0, acc);
        __syncthreads();                       // all X reads done (H aliases X)
        act_store(acc, bb1, sh, r0, c0);
        __syncthreads();                       // H ready

        // ---- layer 2 (K=64) ----
        gemm_rt<HID>(sh, sw2, r0, c0, acc);
        act_store(acc, bb2, sh2, r0, c0);      // H2 disjoint from H reads
        __syncthreads();                       // H2 ready

        // ---- layer 3 (K=64): logits (+bias) -> scratch, row-major 2x float4 ----
        gemm_rt<HID>(sh2, sw3, r0, c0, acc);
        {
            float gv[2][8];
            #pragma unroll
            for (int r = 0; r < 2; ++r)
                #pragma unroll
                for (int cp = 0; cp < 4; ++cp)
                    upk2(acc[r][cp], gv[r][2 * cp], gv[r][2 * cp + 1]);
            #pragma unroll
            for (int r = 0; r < 2; ++r) {
                *reinterpret_cast<float4*>(slg + (r0 + r) * LGS + c0) =
                    make_float4(gv[r][0] + bb3[0], gv[r][1] + bb3[1],
                                gv[r][2] + bb3[2], gv[r][3] + bb3[3]);
                *reinterpret_cast<float4*>(slg + (r0 + r) * LGS + c0 + 4) =
                    make_float4(gv[r][4] + bb3[4], gv[r][5] + bb3[5],
                                gv[r][6] + bb3[6], gv[r][7] + bb3[7]);
            }
        }
        __syncthreads();   // slg ready; also orders the hoisted zero-stores

        // ---- epilogue phase 1: all 512 threads, 4 per row, local top-8 of 16 ----
        {
            const int prow = tid >> 2;      // 0..127
            const int pq   = tid & 3;       // column block of 16
            float v[16];
            #pragma unroll
            for (int g = 0; g < 4; ++g) {
                const float4 t4 = *reinterpret_cast<const float4*>(
                    slg + prow * LGS + pq * 16 + 4 * g);
                v[4 * g] = t4.x; v[4 * g + 1] = t4.y;
                v[4 * g + 2] = t4.z; v[4 * g + 3] = t4.w;
            }
            unsigned used = 0u;
            #pragma unroll
            for (int it = 0; it < TOPK; ++it) {
                float bv = -INFINITY; int bi = 0;
                #pragma unroll
                for (int i = 0; i < 16; ++i) {
                    const bool take = (((used >> i) & 1u) == 0u) && (v[i] > bv);
                    if (take) { bv = v[i]; bi = i; }   // strict > : lowest col on ties
                }
                used |= 1u << bi;
                cand[prow * CSTR + pq * 8 + it] =
                    make_float2(bv, __int_as_float(pq * 16 + bi));
            }
        }
        __syncthreads();

        // ---- epilogue phase 2: threads 0-127 merge 32 cands, softmax, scatter ----
        if (tid < TILE_M) {
            float mv[32]; int mi[32];
            #pragma unroll
            for (int g = 0; g < 16; ++g) {
                const float4 t4 = *reinterpret_cast<const float4*>(
                    (const char*)(cand + tid * CSTR) + 16 * g);
                mv[2 * g]     = t4.x; mi[2 * g]     = __float_as_int(t4.y);
                mv[2 * g + 1] = t4.z; mi[2 * g + 1] = __float_as_int(t4.w);
            }
            unsigned used = 0u;
            float sv[TOPK]; int si[TOPK];
            #pragma unroll
            for (int it = 0; it < TOPK; ++it) {
                float bv = -INFINITY; int bj = 0; int bix = 1 << 30;
                #pragma unroll
                for (int i = 0; i < 32; ++i) {
                    if (((used >> i) & 1u) == 0u) {
                        const bool better = (mv[i] > bv) || (mv[i] == bv && mi[i] < bix);
                        if (better) { bv = mv[i]; bj = i; bix = mi[i]; }
                    }
                }
                used |= 1u << bj; sv[it] = bv; si[it] = bix;
            }
            const float vmax = sv[0];
            float ssum = 0.f;
            #pragma unroll
            for (int t = 0; t < TOPK; ++t) { sv[t] = expf(sv[t] - vmax); ssum += sv[t]; }
            const float inv = 1.0f / ssum;
            float* orow = out + (size_t)(rbase + tid) * KEXP;
            #pragma unroll
            for (int t = 0; t < TOPK; ++t) orow[si[t]] = sv[t] * inv;
        }
        __syncthreads();   // cand/X region free for next tile's gather
    }
}

extern "C" void kernel_launch(void* const* d_in, const int* in_sizes, int n_in,
                              void* d_out, int out_size)
{
    const float* hist   = (const float*)d_in[0];
    const float* num    = (const float*)d_in[1];
    const int*   cat    = (const int*)  d_in[2];
    const int*   region = (const int*)  d_in[3];
    const float* catT   = (const float*)d_in[4];
    const float* regT   = (const float*)d_in[5];
    const float* W1     = (const float*)d_in[6];
    const float* b1     = (const float*)d_in[7];
    const float* W2     = (const float*)d_in[8];
    const float* b2     = (const float*)d_in[9];
    const float* W3     = (const float*)d_in[10];
    const float* b3     = (const float*)d_in[11];
    float* out = (float*)d_out;

    cudaFuncSetAttribute(gating_kernel,
                         cudaFuncAttributeMaxDynamicSharedMemorySize, SMEM_TOTAL);
    gating_kernel<<<148, THREADS, SMEM_TOTAL>>>(
        hist, num, cat, region, catT, regT, W1, b1, W2, b2, W3, b3, out);
}

// round 12
// speedup vs baseline: 2.0138x; 2.0138x over previous
#include <cuda_runtime.h>
#include <math.h>
#include <stdint.h>

#define HIST     50
#define NUMD     32
#define NCAT     8
#define CATD     16
#define REGD     32
#define INDIM    242
#define HID      64
#define KEXP     64
#define TOPK     8
#define HASHB    32768
#define GEOB     4096
#define B_ROWS   524288

#define THREADS  512
#define TILE_M   128
#define NTILES   (B_ROWS / TILE_M)   // 4096
#define XS       132                  // row stride (33 quads: odd mod 8 -> clean STS.128)
#define LGS      68                   // logit scratch row stride (floats)
#define CSTR     34                   // cand row stride (float2 units)

// ---- SMEM layout (byte offsets). H/H2/logits/cand alias the X region. ----
#define OFF_X      0                 // 242*132*4 = 127776
#define OFF_H      0                 //  64*132*4 = 33792 (X dead after L1)
#define OFF_CAND   0                 // 128*34*8 = 34816 (H dead after L2)
#define OFF_H2     34816             //  33792 (ends 68608)
#define OFF_LG     69632             // 128*68*4 = 34816 (ends 104448 < 127776)
#define OFF_W1     127872            // 242*64*4 = 61952
#define OFF_W2     189824            // 16384
#define OFF_W3     206208            // 16384
#define OFF_B1     222592
#define OFF_B2     222848
#define OFF_B3     223104
#define SMEM_TOTAL 223360

typedef unsigned long long u64;

// ---- packed f32x2 helpers (FFMA2: bit-identical fp32 math, 2 FMA/instr) ----
__device__ __forceinline__ u64 pk2(float lo, float hi) {
    u64 r;
    asm("mov.b64 %0, {%1, %2};" : "=l"(r) : "f"(lo), "f"(hi));
    return r;
}
__device__ __forceinline__ void upk2(u64 p, float& lo, float& hi) {
    asm("mov.b64 {%0, %1}, %2;" : "=f"(lo), "=f"(hi) : "l"(p));
}
__device__ __forceinline__ void fma2(u64& d, u64 a, u64 b) {
    asm("fma.rn.f32x2 %0, %1, %2, %0;" : "+l"(d) : "l"(a), "l"(b));
}

__device__ __forceinline__ float gelu_exact(float x) {
    return 0.5f * x * (1.0f + erff(x * 0.70710678118654752440f));
}

// ---- register-tiled GEMM (R8 core): thread = 4 rows x 4 cols, k ascending ----
// A: k-major [K][XS]; W: k-major [K][64].
// acc[r][cp] = packed f32x2 over col pair (c0+2cp, c0+2cp+1) for row r0+r.
template<int K>
__device__ __forceinline__ void gemm_rt(const float* __restrict__ A,
                                        const float* __restrict__ W,
                                        int r0, int c0,
                                        u64 acc[4][2]) {
    #pragma unroll
    for (int r = 0; r < 4; ++r) { acc[r][0] = 0ull; acc[r][1] = 0ull; }

    const float* a = A + r0;
    const float* w = W + c0;
    #pragma unroll 4
    for (int k = 0; k < K; ++k) {
        const float4 xv = *reinterpret_cast<const float4*>(a);
        const ulonglong2 wq = *reinterpret_cast<const ulonglong2*>(w);
        const u64 xd[4] = { pk2(xv.x, xv.x), pk2(xv.y, xv.y),
                            pk2(xv.z, xv.z), pk2(xv.w, xv.w) };
        #pragma unroll
        for (int r = 0; r < 4; ++r) {
            fma2(acc[r][0], xd[r], wq.x);
            fma2(acc[r][1], xd[r], wq.y);
        }
        a += XS; w += 64;
    }
}

// gelu(acc + bias) -> k-major DST[c][r] for the next layer
__device__ __forceinline__ void act_store(const u64 acc[4][2],
                                          float4 bv, float* __restrict__ DST,
                                          int r0, int c0) {
    float gv[4][4];
    #pragma unroll
    for (int r = 0; r < 4; ++r) {
        upk2(acc[r][0], gv[r][0], gv[r][1]);
        upk2(acc[r][1], gv[r][2], gv[r][3]);
    }
    const float bb[4] = { bv.x, bv.y, bv.z, bv.w };
    #pragma unroll
    for (int r = 0; r < 4; ++r)
        #pragma unroll
        for (int c = 0; c < 4; ++c)
            gv[r][c] = gelu_exact(gv[r][c] + bb[c]);
    #pragma unroll
    for (int c = 0; c < 4; ++c)
        *reinterpret_cast<float4*>(DST + (c0 + c) * XS + r0) =
            make_float4(gv[0][c], gv[1][c], gv[2][c], gv[3][c]);
}

__global__ __launch_bounds__(THREADS, 1)
void gating_kernel(const float* __restrict__ hist,
                   const float* __restrict__ num,
                   const int*   __restrict__ cat,
                   const int*   __restrict__ region,
                   const float* __restrict__ catT,
                   const float* __restrict__ regT,
                   const float* __restrict__ W1, const float* __restrict__ b1,
                   const float* __restrict__ W2, const float* __restrict__ b2,
                   const float* __restrict__ W3, const float* __restrict__ b3,
                   float* __restrict__ out)
{
    extern __shared__ __align__(16) char sm[];
    const int tid  = threadIdx.x;
    const int wid  = tid >> 5;
    const int lane = tid & 31;

    float*  sx   = (float*)(sm + OFF_X);
    float*  sh   = (float*)(sm + OFF_H);
    float*  sh2  = (float*)(sm + OFF_H2);
    float*  slg  = (float*)(sm + OFF_LG);
    float2* cand = (float2*)(sm + OFF_CAND);
    float*  sw1  = (float*)(sm + OFF_W1);
    float*  sw2  = (float*)(sm + OFF_W2);
    float*  sw3  = (float*)(sm + OFF_W3);

    // ---- stage weights (k-major, direct copy) + biases ----
    for (int i = tid; i < INDIM * 64 / 4; i += THREADS)
        ((float4*)sw1)[i] = ((const float4*)W1)[i];
    for (int i = tid; i < 64 * 64 / 4; i += THREADS) {
        ((float4*)sw2)[i] = ((const float4*)W2)[i];
        ((float4*)sw3)[i] = ((const float4*)W3)[i];
    }
    if (tid < 64) {
        ((float*)(sm + OFF_B1))[tid] = b1[tid];
        ((float*)(sm + OFF_B2))[tid] = b2[tid];
        ((float*)(sm + OFF_B3))[tid] = b3[tid];
    }
    __syncthreads();

    // GEMM mapping (R8): warp = 16 rows x 32 cols; thread = 4 rows x 4 cols
    const int warpRow = (wid & 7) * 16;
    const int warpCol = (wid >> 3) * 32;
    const int r0 = warpRow + (lane & 3) * 4;
    const int c0 = warpCol + (lane >> 2) * 4;

    const float4 b1v = *(const float4*)((const float*)(sm + OFF_B1) + c0);
    const float4 b2v = *(const float4*)((const float*)(sm + OFF_B2) + c0);
    const float4 b3v = *(const float4*)((const float*)(sm + OFF_B3) + c0);

    for (int tile = blockIdx.x; tile < NTILES; tile += gridDim.x) {
        const int rbase = tile * TILE_M;

        // ---- hoisted zeroing of this tile's output (drains under gather/GEMM) ----
        {
            float4* obase = reinterpret_cast<float4*>(out + (size_t)rbase * KEXP);
            const float4 z = make_float4(0.f, 0.f, 0.f, 0.f);
            #pragma unroll
            for (int j = 0; j < 4; ++j) obase[tid + j * THREADS] = z;
        }

        // ---- transposed gather: lane = feature, packs 4 rows -> one STS.128 ----
        // STS bank-quads: (33*f + r/4) mod 8 consecutive in f -> conflict-free.
        // LDGs: fixed row, lane-consecutive features -> coalesced.
        {
            const int wrow8 = wid * 8;
            #pragma unroll
            for (int g = 0; g < 2; ++g) {
                const int r0g = wrow8 + g * 4;
                const size_t grow = (size_t)(rbase + r0g);
                #pragma unroll
                for (int ch = 0; ch < 8; ++ch) {
                    const int f = ch * 32 + lane;
                    float v[4];
                    bool valid = true;
                    if (f < HIST) {
                        #pragma unroll
                        for (int i = 0; i < 4; ++i)
                            v[i] = hist[(grow + i) * HIST + f];
                    } else if (f < HIST + NUMD) {
                        #pragma unroll
                        for (int i = 0; i < 4; ++i)
                            v[i] = num[(grow + i) * NUMD + (f - HIST)];
                    } else if (f < HIST + NUMD + NCAT * CATD) {
                        const int j = (f - 82) >> 4, d = (f - 82) & 15;
                        #pragma unroll
                        for (int i = 0; i < 4; ++i) {
                            int idx = cat[(grow + i) * NCAT + j];
                            idx = min(max(idx, 0), HASHB - 1);
                            v[i] = catT[((size_t)(j * HASHB + idx)) * CATD + d];
                        }
                    } else if (f < INDIM) {
                        #pragma unroll
                        for (int i = 0; i < 4; ++i) {
                            int rid = region[grow + i];
                            rid = min(max(rid, 0), GEOB - 1);
                            v[i] = regT[(size_t)rid * REGD + (f - 210)];
                        }
                    } else {
                        valid = false;
                    }
                    if (valid)
                        *reinterpret_cast<float4*>(sx + f * XS + r0g) =
                            make_float4(v[0], v[1], v[2], v[3]);
                }
            }
        }
        __syncthreads();

        u64 acc[4][2];

        // ---- layer 1 (K=242) ----
        gemm_rt<INDIM>(sx, sw1, r0, c0, acc);
        __syncthreads();                       // all X reads done (H aliases X)
        act_store(acc, b1v, sh, r0, c0);
        __syncthreads();                       // H ready

        // ---- layer 2 (K=64) ----
        gemm_rt<HID>(sh, sw2, r0, c0, acc);
        act_store(acc, b2v, sh2, r0, c0);      // H2 disjoint from H reads
        __syncthreads();                       // H2 ready

        // ---- layer 3 (K=64): logits (+bias) -> scratch, row-major float4 ----
        gemm_rt<HID>(sh2, sw3, r0, c0, acc);
        {
            const float bb[4] = { b3v.x, b3v.y, b3v.z, b3v.w };
            #pragma unroll
            for (int r = 0; r < 4; ++r) {
                float l0, l1, l2, l3;
                upk2(acc[r][0], l0, l1);
                upk2(acc[r][1], l2, l3);
                *reinterpret_cast<float4*>(slg + (r0 + r) * LGS + c0) =
                    make_float4(l0 + bb[0], l1 + bb[1], l2 + bb[2], l3 + bb[3]);
            }
        }
        __syncthreads();   // slg ready; also orders the hoisted zero-stores

        // ---- epilogue phase 1: all 512 threads, 4 per row, local top-8 of 16 ----
        {
            const int prow = tid >> 2;      // 0..127
            const int pq   = tid & 3;       // column block of 16
            float v[16];
            #pragma unroll
            for (int g = 0; g < 4; ++g) {
                const float4 t4 = *reinterpret_cast<const float4*>(
                    slg + prow * LGS + pq * 16 + 4 * g);
                v[4 * g] = t4.x; v[4 * g + 1] = t4.y;
                v[4 * g + 2] = t4.z; v[4 * g + 3] = t4.w;
            }
            unsigned used = 0u;
            #pragma unroll
            for (int it = 0; it < TOPK; ++it) {
                float bv = -INFINITY; int bi = 0;
                #pragma unroll
                for (int i = 0; i < 16; ++i) {
                    const bool take = (((used >> i) & 1u) == 0u) && (v[i] > bv);
                    if (take) { bv = v[i]; bi = i; }   // strict > : lowest col on ties
                }
                used |= 1u << bi;
                cand[prow * CSTR + pq * 8 + it] =
                    make_float2(bv, __int_as_float(pq * 16 + bi));
            }
        }
        __syncthreads();

        // ---- epilogue phase 2: threads 0-127 merge 32 cands, softmax, scatter ----
        if (tid < TILE_M) {
            float mv[32]; int mi[32];
            #pragma unroll
            for (int g = 0; g < 16; ++g) {
                const float4 t4 = *reinterpret_cast<const float4*>(
                    (const char*)(cand + tid * CSTR) + 16 * g);
                mv[2 * g]     = t4.x; mi[2 * g]     = __float_as_int(t4.y);
                mv[2 * g + 1] = t4.z; mi[2 * g + 1] = __float_as_int(t4.w);
            }
            unsigned used = 0u;
            float sv[TOPK]; int si[TOPK];
            #pragma unroll
            for (int it = 0; it < TOPK; ++it) {
                float bv = -INFINITY; int bj = 0; int bix = 1 << 30;
                #pragma unroll
                for (int i = 0; i < 32; ++i) {
                    if (((used >> i) & 1u) == 0u) {
                        const bool better = (mv[i] > bv) || (mv[i] == bv && mi[i] < bix);
                        if (better) { bv = mv[i]; bj = i; bix = mi[i]; }
                    }
                }
                used |= 1u << bj; sv[it] = bv; si[it] = bix;
            }
            const float vmax = sv[0];
            float ssum = 0.f;
            #pragma unroll
            for (int t = 0; t < TOPK; ++t) { sv[t] = expf(sv[t] - vmax); ssum += sv[t]; }
            const float inv = 1.0f / ssum;
            float* orow = out + (size_t)(rbase + tid) * KEXP;
            #pragma unroll
            for (int t = 0; t < TOPK; ++t) orow[si[t]] = sv[t] * inv;
        }
        __syncthreads();   // cand/X region free for next tile's gather
    }
}

extern "C" void kernel_launch(void* const* d_in, const int* in_sizes, int n_in,
                              void* d_out, int out_size)
{
    const float* hist   = (const float*)d_in[0];
    const float* num    = (const float*)d_in[1];
    const int*   cat    = (const int*)  d_in[2];
    const int*   region = (const int*)  d_in[3];
    const float* catT   = (const float*)d_in[4];
    const float* regT   = (const float*)d_in[5];
    const float* W1     = (const float*)d_in[6];
    const float* b1     = (const float*)d_in[7];
    const float* W2     = (const float*)d_in[8];
    const float* b2     = (const float*)d_in[9];
    const float* W3     = (const float*)d_in[10];
    const float* b3     = (const float*)d_in[11];
    float* out = (float*)d_out;

    cudaFuncSetAttribute(gating_kernel,
                         cudaFuncAttributeMaxDynamicSharedMemorySize, SMEM_TOTAL);
    gating_kernel<<<148, THREADS, SMEM_TOTAL>>>(
        hist, num, cat, region, catT, regT, W1, b1, W2, b2, W3, b3, out);
}